// round 1
// baseline (speedup 1.0000x reference)
#include <cuda_runtime.h>
#include <math.h>
#include <stdint.h>

#define N_NODES 3000
#define IN_DIM  512
#define HID     64
#define HEADS   8
#define CAT     512      // HEADS*HID
#define NCLASS  16
#define MAXDEG  256
#define ALPHA   0.2f

// ---------------- scratch (static device globals; no allocation) -------------
__device__ float g_dinv[N_NODES];
__device__ int   g_cnt [N_NODES];
__device__ int   g_cols[N_NODES * MAXDEG];
__device__ float g_wv  [N_NODES * MAXDEG];
__device__ float g_Wc  [IN_DIM * CAT];          // packed W_heads -> [k][head*64+f]
__device__ float g_H   [N_NODES * CAT];         // h per head, [i][head*64+f]
__device__ float g_src [HEADS * N_NODES];
__device__ float g_dst [HEADS * N_NODES];
__device__ float g_X1  [N_NODES * CAT];         // elu(h') concat, layer-1 output
__device__ float g_H2  [N_NODES * NCLASS];
__device__ float g_s2  [N_NODES];
__device__ float g_d2  [N_NODES];
__device__ float g_Z   [N_NODES * NCLASS];      // elu(elu(layer-2 h'))

__device__ __forceinline__ float elu1(float x) { return x > 0.f ? x : expm1f(x); }
__device__ __forceinline__ float lrelu(float x){ return x >= 0.f ? x : ALPHA * x; }

// ---------------- 1. pack W_heads [8][512][64] -> Wc [512][512] --------------
__global__ void pack_w(const float* __restrict__ W_heads) {
    int k = blockIdx.x;           // 0..511
    int c = threadIdx.x;          // 0..511
    g_Wc[k * CAT + c] = W_heads[(c >> 6) * (IN_DIM * HID) + k * HID + (c & 63)];
}

// ---------------- 2. row degree -> dinv --------------------------------------
__global__ void degree_k(const float* __restrict__ adj) {
    int row = blockIdx.x;
    int tid = threadIdx.x;
    __shared__ float red[256];
    float s = 0.f;
    const float* arow = adj + (size_t)row * N_NODES;
    for (int j = tid; j < N_NODES; j += 256) s += arow[j];
    red[tid] = s;
    __syncthreads();
    for (int o = 128; o; o >>= 1) {
        if (tid < o) red[tid] += red[tid + o];
        __syncthreads();
    }
    if (tid == 0) g_dinv[row] = 1.0f / sqrtf(red[0] + 1.0f);   // +I
}

// ---------------- 3. build ordered edge list (warp per row) ------------------
__global__ void build_edges(const float* __restrict__ adj) {
    int gw   = (blockIdx.x * blockDim.x + threadIdx.x) >> 5;
    int lane = threadIdx.x & 31;
    if (gw >= N_NODES) return;
    int row = gw;
    float di = g_dinv[row];
    const float* arow = adj + (size_t)row * N_NODES;
    int count = 0;
    for (int base = 0; base < N_NODES; base += 32) {
        int j = base + lane;
        float a1 = 0.f;
        if (j < N_NODES) a1 = arow[j] + (j == row ? 1.f : 0.f);
        bool has = a1 > 0.f;
        unsigned msk = __ballot_sync(0xffffffffu, has);
        if (has) {
            int pos = count + __popc(msk & ((1u << lane) - 1u));
            if (pos < MAXDEG) {
                g_cols[row * MAXDEG + pos] = j;
                g_wv [row * MAXDEG + pos] = di * a1 * g_dinv[j];
            }
        }
        count += __popc(msk);
    }
    if (lane == 0) g_cnt[row] = count < MAXDEG ? count : MAXDEG;
}

// ---------------- 4. H = X @ Wc  (3000x512x512 fp32) -------------------------
__global__ void sgemm_H(const float* __restrict__ A) {
    const int BM = 64, BN = 64, BK = 16;
    __shared__ float As[BK][BM];
    __shared__ float Bs[BK][BN];
    int tid = threadIdx.x;                 // 256
    int tx = tid & 15, ty = tid >> 4;
    int brow = blockIdx.y * BM, bcol = blockIdx.x * BN;
    float acc[4][4] = {};
    for (int k0 = 0; k0 < IN_DIM; k0 += BK) {
        {
            int m = tid >> 2, kq = (tid & 3) * 4;
            int row = brow + m;
            float4 v = make_float4(0.f, 0.f, 0.f, 0.f);
            if (row < N_NODES) v = *(const float4*)(A + (size_t)row * IN_DIM + k0 + kq);
            As[kq + 0][m] = v.x; As[kq + 1][m] = v.y;
            As[kq + 2][m] = v.z; As[kq + 3][m] = v.w;
        }
        {
            int r = tid >> 4, c = (tid & 15) * 4;
            *(float4*)&Bs[r][c] = *(const float4*)(g_Wc + (size_t)(k0 + r) * CAT + bcol + c);
        }
        __syncthreads();
#pragma unroll
        for (int k = 0; k < BK; k++) {
            float a[4], b[4];
            *(float4*)a = *(float4*)&As[k][ty * 4];
            *(float4*)b = *(float4*)&Bs[k][tx * 4];
#pragma unroll
            for (int i = 0; i < 4; i++)
#pragma unroll
                for (int j = 0; j < 4; j++)
                    acc[i][j] += a[i] * b[j];
        }
        __syncthreads();
    }
#pragma unroll
    for (int i = 0; i < 4; i++) {
        int row = brow + ty * 4 + i;
        if (row < N_NODES)
#pragma unroll
            for (int j = 0; j < 4; j++)
                g_H[(size_t)row * CAT + bcol + tx * 4 + j] = acc[i][j];
    }
}

// ---------------- 5. src/dst per head ----------------------------------------
__global__ void srcdst1(const float* __restrict__ a_heads) {
    int i = blockIdx.x;
    int head = threadIdx.x >> 5, lane = threadIdx.x & 31;
    const float* h = g_H + (size_t)i * CAT + head * HID;
    const float* a = a_heads + head * (2 * HID);
    float s = h[lane] * a[lane]      + h[lane + 32] * a[lane + 32];
    float d = h[lane] * a[64 + lane] + h[lane + 32] * a[96 + lane];
#pragma unroll
    for (int o = 16; o; o >>= 1) {
        s += __shfl_xor_sync(0xffffffffu, s, o);
        d += __shfl_xor_sync(0xffffffffu, d, o);
    }
    if (lane == 0) {
        g_src[head * N_NODES + i] = s;
        g_dst[head * N_NODES + i] = d;
    }
}

// ---------------- 6. layer-1 sparse attention (block/row, warp/head) ---------
__global__ void attn1() {
    int i = blockIdx.x;
    int tid = threadIdx.x;
    int head = tid >> 5, lane = tid & 31;
    __shared__ int   s_cols[MAXDEG];
    __shared__ float s_w[MAXDEG];
    __shared__ float s_p[HEADS][MAXDEG];
    int n = g_cnt[i];
    for (int k = tid; k < n; k += 256) {
        s_cols[k] = g_cols[i * MAXDEG + k];
        s_w[k]    = g_wv [i * MAXDEG + k];
    }
    __syncthreads();

    float si = g_src[head * N_NODES + i];
    float m = -1e30f;
    for (int k = lane; k < n; k += 32) {
        float e = lrelu(si + g_dst[head * N_NODES + s_cols[k]]);
        s_p[head][k] = e;
        m = fmaxf(m, e);
    }
#pragma unroll
    for (int o = 16; o; o >>= 1) m = fmaxf(m, __shfl_xor_sync(0xffffffffu, m, o));
    float s = 0.f;
    for (int k = lane; k < n; k += 32) {
        float p = __expf(s_p[head][k] - m);
        s_p[head][k] = p;
        s += p;
    }
#pragma unroll
    for (int o = 16; o; o >>= 1) s += __shfl_xor_sync(0xffffffffu, s, o);
    float inv = 1.f / s;
    __syncwarp();

    float acc0 = 0.f, acc1 = 0.f;
    for (int k = 0; k < n; k++) {
        int j = s_cols[k];
        float coef = s_p[head][k] * inv * s_w[k];
        const float* hj = g_H + (size_t)j * CAT + head * HID;
        acc0 = fmaf(coef, hj[lane],      acc0);
        acc1 = fmaf(coef, hj[lane + 32], acc1);
    }
    g_X1[(size_t)i * CAT + head * HID + lane]      = elu1(acc0);
    g_X1[(size_t)i * CAT + head * HID + lane + 32] = elu1(acc1);
}

// ---------------- 7. H2 = X1 @ W_out, src2/dst2 ------------------------------
__global__ void h2_srcdst(const float* __restrict__ W_out,
                          const float* __restrict__ a_out) {
    int i = blockIdx.x, tid = threadIdx.x;
    __shared__ float sx[CAT];
    __shared__ float sp[16][17];
    __shared__ float sh[NCLASS];
    sx[tid]       = g_X1[(size_t)i * CAT + tid];
    sx[tid + 256] = g_X1[(size_t)i * CAT + tid + 256];
    __syncthreads();
    int c = tid & 15, chunk = tid >> 4;
    float p = 0.f;
    int k0 = chunk * 32;
#pragma unroll 8
    for (int k = k0; k < k0 + 32; k++) p = fmaf(sx[k], __ldg(W_out + k * NCLASS + c), p);
    sp[chunk][c] = p;
    __syncthreads();
    if (tid < NCLASS) {
        float v = 0.f;
#pragma unroll
        for (int q = 0; q < 16; q++) v += sp[q][tid];
        g_H2[i * NCLASS + tid] = v;
        sh[tid] = v;
    }
    __syncthreads();
    if (tid == 0) {
        float s = 0.f, d = 0.f;
#pragma unroll
        for (int cc = 0; cc < NCLASS; cc++) {
            s = fmaf(sh[cc], __ldg(a_out + cc), s);
            d = fmaf(sh[cc], __ldg(a_out + NCLASS + cc), d);
        }
        g_s2[i] = s;
        g_d2[i] = d;
    }
}

// ---------------- 8. layer-2 sparse attention (warp per row) -----------------
__global__ void attn2() {
    int w = threadIdx.x >> 5, lane = threadIdx.x & 31;
    int i = blockIdx.x * 4 + w;
    __shared__ int   s_c[4][MAXDEG];
    __shared__ float s_w[4][MAXDEG];
    __shared__ float s_p[4][MAXDEG];
    if (i >= N_NODES) return;
    int n = g_cnt[i];
    float si = g_s2[i];
    float m = -1e30f;
    for (int k = lane; k < n; k += 32) {
        int j = g_cols[i * MAXDEG + k];
        s_c[w][k] = j;
        s_w[w][k] = g_wv[i * MAXDEG + k];
        float e = lrelu(si + g_d2[j]);
        s_p[w][k] = e;
        m = fmaxf(m, e);
    }
#pragma unroll
    for (int o = 16; o; o >>= 1) m = fmaxf(m, __shfl_xor_sync(0xffffffffu, m, o));
    float s = 0.f;
    for (int k = lane; k < n; k += 32) {
        float p = __expf(s_p[w][k] - m);
        s_p[w][k] = p;
        s += p;
    }
#pragma unroll
    for (int o = 16; o; o >>= 1) s += __shfl_xor_sync(0xffffffffu, s, o);
    float inv = 1.f / s;
    __syncwarp();
    if (lane < NCLASS) {
        float acc = 0.f;
        for (int k = 0; k < n; k++) {
            float coef = s_p[w][k] * inv * s_w[w][k];
            acc = fmaf(coef, g_H2[s_c[w][k] * NCLASS + lane], acc);
        }
        g_Z[i * NCLASS + lane] = elu1(elu1(acc));   // elu(gat) wrapped in elu
    }
}

// ---------------- 9. FC head + log_softmax (warp per row) --------------------
__global__ void head_k(const float* __restrict__ FC1,
                       const float* __restrict__ FC2,
                       float* __restrict__ out) {
    int w = threadIdx.x >> 5, lane = threadIdx.x & 31;
    int row = blockIdx.x * 8 + w;
    if (row >= N_NODES) return;
    float z = (lane < NCLASS) ? g_Z[row * NCLASS + lane] : 0.f;
    // y1 = elu(z @ FC1^T)
    float y1 = 0.f;
#pragma unroll
    for (int k = 0; k < NCLASS; k++) {
        float zk = __shfl_sync(0xffffffffu, z, k);
        if (lane < NCLASS) y1 = fmaf(zk, __ldg(FC1 + lane * NCLASS + k), y1);
    }
    y1 = elu1(y1);
    float y2 = 0.f;
#pragma unroll
    for (int k = 0; k < NCLASS; k++) {
        float yk = __shfl_sync(0xffffffffu, y1, k);
        if (lane < NCLASS) y2 = fmaf(yk, __ldg(FC2 + lane * NCLASS + k), y2);
    }
    y2 = elu1(y2);
    // log_softmax over the 16-lane group
    float v = (lane < NCLASS) ? y2 : -1e30f;
#pragma unroll
    for (int o = 8; o; o >>= 1) v = fmaxf(v, __shfl_xor_sync(0xffffffffu, v, o));
    float e = (lane < NCLASS) ? expf(y2 - v) : 0.f;
    float sum = e;
#pragma unroll
    for (int o = 8; o; o >>= 1) sum += __shfl_xor_sync(0xffffffffu, sum, o);
    if (lane < NCLASS) out[row * NCLASS + lane] = y2 - v - logf(sum);
}

// ---------------- launcher ---------------------------------------------------
extern "C" void kernel_launch(void* const* d_in, const int* in_sizes, int n_in,
                              void* d_out, int out_size) {
    const float* adj     = (const float*)d_in[0];
    const float* feat    = (const float*)d_in[1];
    const float* W_heads = (const float*)d_in[2];
    const float* a_heads = (const float*)d_in[3];
    const float* W_out   = (const float*)d_in[4];
    const float* a_out   = (const float*)d_in[5];
    const float* FC1     = (const float*)d_in[6];
    const float* FC2     = (const float*)d_in[7];
    float* out = (float*)d_out;

    pack_w     <<<IN_DIM, CAT>>>(W_heads);
    degree_k   <<<N_NODES, 256>>>(adj);
    build_edges<<<(N_NODES * 32 + 255) / 256, 256>>>(adj);
    sgemm_H    <<<dim3(CAT / 64, (N_NODES + 63) / 64), 256>>>(feat);
    srcdst1    <<<N_NODES, 256>>>(a_heads);
    attn1      <<<N_NODES, 256>>>();
    h2_srcdst  <<<N_NODES, 256>>>(W_out, a_out);
    attn2      <<<(N_NODES + 3) / 4, 128>>>();
    head_k     <<<(N_NODES + 7) / 8, 256>>>(FC1, FC2, out);
}

// round 2
// speedup vs baseline: 1.1210x; 1.1210x over previous
#include <cuda_runtime.h>
#include <math.h>
#include <stdint.h>

#define N_NODES 3000
#define IN_DIM  512
#define HID     64
#define HEADS   8
#define CAT     512      // HEADS*HID
#define NCLASS  16
#define MAXDEG  256
#define ALPHA   0.2f

// ---------------- scratch (static device globals; no allocation) -------------
__device__ float g_rowsum[N_NODES];
__device__ float g_dinv[N_NODES];
__device__ int   g_cnt [N_NODES];
__device__ int   g_cols[N_NODES * MAXDEG];
__device__ float g_wv  [N_NODES * MAXDEG];
__device__ float g_Wc  [IN_DIM * CAT];          // packed W_heads -> [k][head*64+f]
__device__ float g_H   [N_NODES * CAT];         // h per head, [i][head*64+f]
__device__ float g_src [HEADS * N_NODES];
__device__ float g_dst [HEADS * N_NODES];
__device__ float g_X1  [N_NODES * CAT];         // elu(h') concat, layer-1 output
__device__ float g_H2  [N_NODES * NCLASS];
__device__ float g_s2  [N_NODES];
__device__ float g_d2  [N_NODES];
__device__ float g_Z   [N_NODES * NCLASS];      // elu(elu(layer-2 h'))

__device__ __forceinline__ float elu1(float x) { return x > 0.f ? x : expm1f(x); }
__device__ __forceinline__ float lrelu(float x){ return x >= 0.f ? x : ALPHA * x; }

// ---------------- 1. pack W_heads [8][512][64] -> Wc [512][512] --------------
__global__ void pack_w(const float* __restrict__ W_heads) {
    int k = blockIdx.x;           // 0..511
    int c = threadIdx.x;          // 0..511
    g_Wc[k * CAT + c] = W_heads[(c >> 6) * (IN_DIM * HID) + k * HID + (c & 63)];
}

// ---------------- 2. single-pass edge build: cols, a1 vals, rowsum -----------
// One 36MB scan (float4). Ordering (t-within-lane, lane) is deterministic.
__global__ void build_edges(const float* __restrict__ adj) {
    int gw   = (blockIdx.x * blockDim.x + threadIdx.x) >> 5;
    int lane = threadIdx.x & 31;
    if (gw >= N_NODES) return;
    int row = gw;
    const float4* arow4 = (const float4*)(adj + (size_t)row * N_NODES);
    int count = 0;
    float rsum = 0.f;
    const int NQ = N_NODES / 4;   // 750
    for (int base = 0; base < NQ; base += 32) {
        int q = base + lane;
        float a[4] = {0.f, 0.f, 0.f, 0.f};
        if (q < NQ) {
            float4 v = arow4[q];
            a[0] = v.x; a[1] = v.y; a[2] = v.z; a[3] = v.w;
            int j0 = q * 4;
            if (row >= j0 && row < j0 + 4) a[row - j0] += 1.f;  // +I
        }
        rsum += a[0] + a[1] + a[2] + a[3];
        int j0 = q * 4;
#pragma unroll
        for (int t = 0; t < 4; t++) {
            bool has = a[t] > 0.f;
            unsigned msk = __ballot_sync(0xffffffffu, has);
            if (has) {
                int pos = count + __popc(msk & ((1u << lane) - 1u));
                if (pos < MAXDEG) {
                    g_cols[row * MAXDEG + pos] = j0 + t;
                    g_wv [row * MAXDEG + pos] = a[t];   // raw a1, scaled later
                }
            }
            count += __popc(msk);
        }
    }
#pragma unroll
    for (int o = 16; o; o >>= 1) rsum += __shfl_xor_sync(0xffffffffu, rsum, o);
    if (lane == 0) {
        g_cnt[row] = count < MAXDEG ? count : MAXDEG;
        g_rowsum[row] = rsum;
    }
}

__global__ void dinv_k() {
    int i = blockIdx.x * blockDim.x + threadIdx.x;
    if (i < N_NODES) g_dinv[i] = 1.0f / sqrtf(g_rowsum[i]);
}

// scale edge weights: wv *= dinv_i * dinv_j  (E entries only)
__global__ void wv_k() {
    int i = blockIdx.x;
    float di = g_dinv[i];
    int n = g_cnt[i];
    for (int k = threadIdx.x; k < n; k += blockDim.x)
        g_wv[i * MAXDEG + k] *= di * g_dinv[g_cols[i * MAXDEG + k]];
}

// ---------------- 3. H = X @ Wc  (3000x512x512 fp32), 128x64 double-buffered -
#define BM 128
#define BN 64
#define BK 16
__global__ __launch_bounds__(256) void sgemm_H(const float* __restrict__ A) {
    __shared__ float As[2][BK][BM];   // 16KB
    __shared__ float Bs[2][BK][BN];   // 8KB
    int tid = threadIdx.x;
    int tx = tid & 15, ty = tid >> 4;
    int brow = blockIdx.y * BM, bcol = blockIdx.x * BN;
    int am = tid >> 1, ak = (tid & 1) * 8;
    int br = tid >> 4, bc = (tid & 15) * 4;

    const float* Aptr = A + (size_t)(brow + am) * IN_DIM + ak;
    bool aok = (brow + am) < N_NODES;
    const float* Bptr = g_Wc + (size_t)br * CAT + bcol + bc;
    const float4 z4 = make_float4(0.f, 0.f, 0.f, 0.f);

    float4 ra0 = aok ? *(const float4*)(Aptr)     : z4;
    float4 ra1 = aok ? *(const float4*)(Aptr + 4) : z4;
    float4 rb  = *(const float4*)(Bptr);
    As[0][ak + 0][am] = ra0.x; As[0][ak + 1][am] = ra0.y;
    As[0][ak + 2][am] = ra0.z; As[0][ak + 3][am] = ra0.w;
    As[0][ak + 4][am] = ra1.x; As[0][ak + 5][am] = ra1.y;
    As[0][ak + 6][am] = ra1.z; As[0][ak + 7][am] = ra1.w;
    *(float4*)&Bs[0][br][bc] = rb;
    __syncthreads();

    float acc[8][4] = {};
    int cur = 0;
    for (int k0 = BK; k0 <= IN_DIM; k0 += BK) {
        bool last = (k0 == IN_DIM);
        if (!last) {
            ra0 = aok ? *(const float4*)(Aptr + k0)     : z4;
            ra1 = aok ? *(const float4*)(Aptr + k0 + 4) : z4;
            rb  = *(const float4*)(Bptr + (size_t)k0 * CAT);
        }
#pragma unroll
        for (int k = 0; k < BK; k++) {
            float4 x0 = *(float4*)&As[cur][k][ty * 8];
            float4 x1 = *(float4*)&As[cur][k][ty * 8 + 4];
            float4 y  = *(float4*)&Bs[cur][k][tx * 4];
            float xa[8] = {x0.x, x0.y, x0.z, x0.w, x1.x, x1.y, x1.z, x1.w};
            float yb[4] = {y.x, y.y, y.z, y.w};
#pragma unroll
            for (int i = 0; i < 8; i++)
#pragma unroll
                for (int j = 0; j < 4; j++)
                    acc[i][j] = fmaf(xa[i], yb[j], acc[i][j]);
        }
        if (!last) {
            int nxt = cur ^ 1;
            As[nxt][ak + 0][am] = ra0.x; As[nxt][ak + 1][am] = ra0.y;
            As[nxt][ak + 2][am] = ra0.z; As[nxt][ak + 3][am] = ra0.w;
            As[nxt][ak + 4][am] = ra1.x; As[nxt][ak + 5][am] = ra1.y;
            As[nxt][ak + 6][am] = ra1.z; As[nxt][ak + 7][am] = ra1.w;
            *(float4*)&Bs[nxt][br][bc] = rb;
        }
        __syncthreads();
        cur ^= 1;
    }
#pragma unroll
    for (int i = 0; i < 8; i++) {
        int row = brow + ty * 8 + i;
        if (row < N_NODES) {
            float4 o = make_float4(acc[i][0], acc[i][1], acc[i][2], acc[i][3]);
            *(float4*)(g_H + (size_t)row * CAT + bcol + tx * 4) = o;
        }
    }
}

// ---------------- 4. src/dst per head ----------------------------------------
__global__ void srcdst1(const float* __restrict__ a_heads) {
    int i = blockIdx.x;
    int head = threadIdx.x >> 5, lane = threadIdx.x & 31;
    const float* h = g_H + (size_t)i * CAT + head * HID;
    const float* a = a_heads + head * (2 * HID);
    float s = h[lane] * a[lane]      + h[lane + 32] * a[lane + 32];
    float d = h[lane] * a[64 + lane] + h[lane + 32] * a[96 + lane];
#pragma unroll
    for (int o = 16; o; o >>= 1) {
        s += __shfl_xor_sync(0xffffffffu, s, o);
        d += __shfl_xor_sync(0xffffffffu, d, o);
    }
    if (lane == 0) {
        g_src[head * N_NODES + i] = s;
        g_dst[head * N_NODES + i] = d;
    }
}

// ---------------- 5. layer-1 sparse attention (block/row, warp/head) ---------
__global__ void attn1() {
    int i = blockIdx.x;
    int tid = threadIdx.x;
    int head = tid >> 5, lane = tid & 31;
    __shared__ int   s_cols[MAXDEG];
    __shared__ float s_w[MAXDEG];
    __shared__ float s_p[HEADS][MAXDEG];
    int n = g_cnt[i];
    for (int k = tid; k < n; k += 256) {
        s_cols[k] = g_cols[i * MAXDEG + k];
        s_w[k]    = g_wv [i * MAXDEG + k];
    }
    __syncthreads();

    float si = g_src[head * N_NODES + i];
    float m = -1e30f;
    for (int k = lane; k < n; k += 32) {
        float e = lrelu(si + g_dst[head * N_NODES + s_cols[k]]);
        s_p[head][k] = e;
        m = fmaxf(m, e);
    }
#pragma unroll
    for (int o = 16; o; o >>= 1) m = fmaxf(m, __shfl_xor_sync(0xffffffffu, m, o));
    float s = 0.f;
    for (int k = lane; k < n; k += 32) {
        float p = __expf(s_p[head][k] - m);
        s_p[head][k] = p;
        s += p;
    }
#pragma unroll
    for (int o = 16; o; o >>= 1) s += __shfl_xor_sync(0xffffffffu, s, o);
    float inv = 1.f / s;
    __syncwarp();

    const float2* Hb = (const float2*)g_H;
    float2 acc = make_float2(0.f, 0.f);
#pragma unroll 2
    for (int k = 0; k < n; k++) {
        int j = s_cols[k];
        float coef = s_p[head][k] * inv * s_w[k];
        float2 v = Hb[(size_t)j * (CAT / 2) + head * 32 + lane];
        acc.x = fmaf(coef, v.x, acc.x);
        acc.y = fmaf(coef, v.y, acc.y);
    }
    float2 o = make_float2(elu1(acc.x), elu1(acc.y));
    ((float2*)g_X1)[(size_t)i * (CAT / 2) + head * 32 + lane] = o;
}

// ---------------- 6. H2 = X1 @ W_out, src2/dst2 ------------------------------
__global__ void h2_srcdst(const float* __restrict__ W_out,
                          const float* __restrict__ a_out) {
    int i = blockIdx.x, tid = threadIdx.x;
    __shared__ float sx[CAT];
    __shared__ float sp[16][17];
    __shared__ float sh[NCLASS];
    sx[tid]       = g_X1[(size_t)i * CAT + tid];
    sx[tid + 256] = g_X1[(size_t)i * CAT + tid + 256];
    __syncthreads();
    int c = tid & 15, chunk = tid >> 4;
    float p = 0.f;
    int k0 = chunk * 32;
#pragma unroll 8
    for (int k = k0; k < k0 + 32; k++) p = fmaf(sx[k], __ldg(W_out + k * NCLASS + c), p);
    sp[chunk][c] = p;
    __syncthreads();
    if (tid < NCLASS) {
        float v = 0.f;
#pragma unroll
        for (int q = 0; q < 16; q++) v += sp[q][tid];
        g_H2[i * NCLASS + tid] = v;
        sh[tid] = v;
    }
    __syncthreads();
    if (tid == 0) {
        float s = 0.f, d = 0.f;
#pragma unroll
        for (int cc = 0; cc < NCLASS; cc++) {
            s = fmaf(sh[cc], __ldg(a_out + cc), s);
            d = fmaf(sh[cc], __ldg(a_out + NCLASS + cc), d);
        }
        g_s2[i] = s;
        g_d2[i] = d;
    }
}

// ---------------- 7. layer-2 sparse attention (warp per row) -----------------
__global__ void attn2() {
    int w = threadIdx.x >> 5, lane = threadIdx.x & 31;
    int i = blockIdx.x * 4 + w;
    __shared__ int   s_c[4][MAXDEG];
    __shared__ float s_w[4][MAXDEG];
    __shared__ float s_p[4][MAXDEG];
    if (i >= N_NODES) return;
    int n = g_cnt[i];
    float si = g_s2[i];
    float m = -1e30f;
    for (int k = lane; k < n; k += 32) {
        int j = g_cols[i * MAXDEG + k];
        s_c[w][k] = j;
        s_w[w][k] = g_wv[i * MAXDEG + k];
        float e = lrelu(si + g_d2[j]);
        s_p[w][k] = e;
        m = fmaxf(m, e);
    }
#pragma unroll
    for (int o = 16; o; o >>= 1) m = fmaxf(m, __shfl_xor_sync(0xffffffffu, m, o));
    float s = 0.f;
    for (int k = lane; k < n; k += 32) {
        float p = __expf(s_p[w][k] - m);
        s_p[w][k] = p;
        s += p;
    }
#pragma unroll
    for (int o = 16; o; o >>= 1) s += __shfl_xor_sync(0xffffffffu, s, o);
    float inv = 1.f / s;
    __syncwarp();
    if (lane < NCLASS) {
        float acc = 0.f;
        for (int k = 0; k < n; k++) {
            float coef = s_p[w][k] * inv * s_w[w][k];
            acc = fmaf(coef, g_H2[s_c[w][k] * NCLASS + lane], acc);
        }
        g_Z[i * NCLASS + lane] = elu1(elu1(acc));
    }
}

// ---------------- 8. FC head + log_softmax (warp per row) --------------------
__global__ void head_k(const float* __restrict__ FC1,
                       const float* __restrict__ FC2,
                       float* __restrict__ out) {
    int w = threadIdx.x >> 5, lane = threadIdx.x & 31;
    int row = blockIdx.x * 8 + w;
    if (row >= N_NODES) return;
    float z = (lane < NCLASS) ? g_Z[row * NCLASS + lane] : 0.f;
    float y1 = 0.f;
#pragma unroll
    for (int k = 0; k < NCLASS; k++) {
        float zk = __shfl_sync(0xffffffffu, z, k);
        if (lane < NCLASS) y1 = fmaf(zk, __ldg(FC1 + lane * NCLASS + k), y1);
    }
    y1 = elu1(y1);
    float y2 = 0.f;
#pragma unroll
    for (int k = 0; k < NCLASS; k++) {
        float yk = __shfl_sync(0xffffffffu, y1, k);
        if (lane < NCLASS) y2 = fmaf(yk, __ldg(FC2 + lane * NCLASS + k), y2);
    }
    y2 = elu1(y2);
    float v = (lane < NCLASS) ? y2 : -1e30f;
#pragma unroll
    for (int o = 8; o; o >>= 1) v = fmaxf(v, __shfl_xor_sync(0xffffffffu, v, o));
    float e = (lane < NCLASS) ? expf(y2 - v) : 0.f;
    float sum = e;
#pragma unroll
    for (int o = 8; o; o >>= 1) sum += __shfl_xor_sync(0xffffffffu, sum, o);
    if (lane < NCLASS) out[row * NCLASS + lane] = y2 - v - logf(sum);
}

// ---------------- launcher ---------------------------------------------------
extern "C" void kernel_launch(void* const* d_in, const int* in_sizes, int n_in,
                              void* d_out, int out_size) {
    const float* adj     = (const float*)d_in[0];
    const float* feat    = (const float*)d_in[1];
    const float* W_heads = (const float*)d_in[2];
    const float* a_heads = (const float*)d_in[3];
    const float* W_out   = (const float*)d_in[4];
    const float* a_out   = (const float*)d_in[5];
    const float* FC1     = (const float*)d_in[6];
    const float* FC2     = (const float*)d_in[7];
    float* out = (float*)d_out;

    pack_w     <<<IN_DIM, CAT>>>(W_heads);
    build_edges<<<(N_NODES * 32 + 255) / 256, 256>>>(adj);
    dinv_k     <<<(N_NODES + 255) / 256, 256>>>();
    wv_k       <<<N_NODES, 64>>>();
    sgemm_H    <<<dim3(CAT / BN, (N_NODES + BM - 1) / BM), 256>>>(feat);
    srcdst1    <<<N_NODES, 256>>>(a_heads);
    attn1      <<<N_NODES, 256>>>();
    h2_srcdst  <<<N_NODES, 256>>>(W_out, a_out);
    attn2      <<<(N_NODES + 3) / 4, 128>>>();
    head_k     <<<(N_NODES + 7) / 8, 256>>>(FC1, FC2, out);
}

// round 3
// speedup vs baseline: 1.3659x; 1.2185x over previous
#include <cuda_runtime.h>
#include <math.h>
#include <stdint.h>

#define N_NODES 3000
#define IN_DIM  512
#define HID     64
#define HEADS   8
#define CAT     512      // HEADS*HID
#define NCLASS  16
#define MAXDEG  256
#define ALPHA   0.2f

// ---------------- scratch (static device globals; no allocation) -------------
__device__ float g_dinv[N_NODES];
__device__ int   g_cnt [N_NODES];
__device__ int   g_cols[N_NODES * MAXDEG];
__device__ float g_wv  [N_NODES * MAXDEG];
__device__ float g_Wc  [IN_DIM * CAT];          // packed W_heads -> [k][head*64+f]
__device__ float g_H   [N_NODES * CAT];         // h per head, [i][head*64+f]
__device__ float g_srcT[N_NODES * HEADS];       // [node][head]
__device__ float g_dstT[N_NODES * HEADS];       // [node][head]
__device__ float g_X1  [N_NODES * CAT];
__device__ float g_H2  [N_NODES * NCLASS];
__device__ float g_s2  [N_NODES];
__device__ float g_d2  [N_NODES];
__device__ float g_Z   [N_NODES * NCLASS];

__device__ __forceinline__ float elu1(float x) { return x > 0.f ? x : expm1f(x); }
__device__ __forceinline__ float lrelu(float x){ return x >= 0.f ? x : ALPHA * x; }

// ---------------- 1. pack W_heads [8][512][64] -> Wc [512][512] --------------
__global__ void pack_w(const float* __restrict__ W_heads) {
    int k = blockIdx.x;
    int c = threadIdx.x;
    g_Wc[k * CAT + c] = W_heads[(c >> 6) * (IN_DIM * HID) + k * HID + (c & 63)];
}

// ---------------- 2. edge build: 4 warps/row, column-segment partition -------
// Deterministic: edge order == column order (segment-major, ballot within).
#define SEGQ 188   // float4-quads per warp segment (last gets 186)
__global__ __launch_bounds__(128) void build_edges(const float* __restrict__ adj) {
    int row  = blockIdx.x;
    int tid  = threadIdx.x;
    int w    = tid >> 5, lane = tid & 31;
    __shared__ int   s_bufc[4][128];
    __shared__ float s_bufv[4][128];
    __shared__ int   s_cnt[4];
    __shared__ float s_sum[4];

    const float4* arow4 = (const float4*)(adj + (size_t)row * N_NODES);
    const int NQ = N_NODES / 4;                 // 750
    int q0 = w * SEGQ;
    int q1 = min(q0 + SEGQ, NQ);

    int cnt = 0;
    float rsum = 0.f;
    for (int base = q0; base < q1; base += 32) {
        int q = base + lane;
        bool valid = q < q1;
        float a[4] = {0.f, 0.f, 0.f, 0.f};
        int j0 = q * 4;
        if (valid) {
            float4 v = arow4[q];
            a[0] = v.x; a[1] = v.y; a[2] = v.z; a[3] = v.w;
            if (row >= j0 && row < j0 + 4) a[row - j0] += 1.f;   // +I
        }
        rsum += a[0] + a[1] + a[2] + a[3];
#pragma unroll
        for (int t = 0; t < 4; t++) {
            bool has = valid && (a[t] > 0.f);
            unsigned msk = __ballot_sync(0xffffffffu, has);
            if (has) {
                int pos = cnt + __popc(msk & ((1u << lane) - 1u));
                if (pos < 128) {
                    s_bufc[w][pos] = j0 + t;
                    s_bufv[w][pos] = a[t];
                }
            }
            cnt += __popc(msk);
        }
    }
#pragma unroll
    for (int o = 16; o; o >>= 1) rsum += __shfl_xor_sync(0xffffffffu, rsum, o);
    if (lane == 0) { s_cnt[w] = cnt; s_sum[w] = rsum; }
    __syncthreads();

    int c0 = 0;
#pragma unroll
    for (int t = 0; t < 4; t++) if (t < w) c0 += s_cnt[t];
    int myc = min(s_cnt[w], 128);
    for (int k = lane; k < myc; k += 32) {
        int pos = c0 + k;
        if (pos < MAXDEG) {
            g_cols[row * MAXDEG + pos] = s_bufc[w][k];
            g_wv [row * MAXDEG + pos] = s_bufv[w][k];
        }
    }
    if (tid == 0) {
        int tot = s_cnt[0] + s_cnt[1] + s_cnt[2] + s_cnt[3];
        g_cnt[row]  = tot < MAXDEG ? tot : MAXDEG;
        g_dinv[row] = rsqrtf(s_sum[0] + s_sum[1] + s_sum[2] + s_sum[3]);
    }
}

// ---------------- 3. scale edge weights (flat, coalesced) --------------------
__global__ void wv_k() {
    int idx = blockIdx.x * blockDim.x + threadIdx.x;
    if (idx >= N_NODES * MAXDEG) return;
    int i = idx >> 8, k = idx & (MAXDEG - 1);
    if (k < g_cnt[i])
        g_wv[idx] *= g_dinv[i] * g_dinv[g_cols[idx]];
}

// ---------------- 4. H = X @ Wc, 64x64 warp-tiled, double-buffered -----------
#define BM 64
#define BN 64
#define BK 16
__global__ __launch_bounds__(128) void sgemm_H(const float* __restrict__ A) {
    __shared__ float As[2][BK][BM];
    __shared__ float Bs[2][BK][BN];
    int tid = threadIdx.x;
    int warp = tid >> 5, lane = tid & 31;
    int wr = (warp >> 1) * 32, wc = (warp & 1) * 32;
    int lr = lane >> 3, lc = lane & 7;
    int brow = blockIdx.y * BM, bcol = blockIdx.x * BN;

    int am = tid >> 1, ak = (tid & 1) * 8;
    int br = tid >> 3, bc = (tid & 7) * 8;
    const float* Aptr = A + (size_t)(brow + am) * IN_DIM + ak;
    bool aok = (brow + am) < N_NODES;
    const float* Bptr = g_Wc + (size_t)br * CAT + bcol + bc;
    const float4 z4 = make_float4(0.f, 0.f, 0.f, 0.f);

    float4 ra0 = aok ? *(const float4*)(Aptr)     : z4;
    float4 ra1 = aok ? *(const float4*)(Aptr + 4) : z4;
    float4 rb0 = *(const float4*)(Bptr);
    float4 rb1 = *(const float4*)(Bptr + 4);
    As[0][ak + 0][am] = ra0.x; As[0][ak + 1][am] = ra0.y;
    As[0][ak + 2][am] = ra0.z; As[0][ak + 3][am] = ra0.w;
    As[0][ak + 4][am] = ra1.x; As[0][ak + 5][am] = ra1.y;
    As[0][ak + 6][am] = ra1.z; As[0][ak + 7][am] = ra1.w;
    *(float4*)&Bs[0][br][bc]     = rb0;
    *(float4*)&Bs[0][br][bc + 4] = rb1;
    __syncthreads();

    float acc[8][4] = {};
    int cur = 0;
    for (int k0 = BK; k0 <= IN_DIM; k0 += BK) {
        bool last = (k0 == IN_DIM);
        if (!last) {
            ra0 = aok ? *(const float4*)(Aptr + k0)     : z4;
            ra1 = aok ? *(const float4*)(Aptr + k0 + 4) : z4;
            rb0 = *(const float4*)(Bptr + (size_t)k0 * CAT);
            rb1 = *(const float4*)(Bptr + (size_t)k0 * CAT + 4);
        }
#pragma unroll
        for (int k = 0; k < BK; k++) {
            float4 x0 = *(float4*)&As[cur][k][wr + lr * 8];
            float4 x1 = *(float4*)&As[cur][k][wr + lr * 8 + 4];
            float4 y  = *(float4*)&Bs[cur][k][wc + lc * 4];
            float xa[8] = {x0.x, x0.y, x0.z, x0.w, x1.x, x1.y, x1.z, x1.w};
            float yb[4] = {y.x, y.y, y.z, y.w};
#pragma unroll
            for (int i = 0; i < 8; i++)
#pragma unroll
                for (int j = 0; j < 4; j++)
                    acc[i][j] = fmaf(xa[i], yb[j], acc[i][j]);
        }
        if (!last) {
            int nxt = cur ^ 1;
            As[nxt][ak + 0][am] = ra0.x; As[nxt][ak + 1][am] = ra0.y;
            As[nxt][ak + 2][am] = ra0.z; As[nxt][ak + 3][am] = ra0.w;
            As[nxt][ak + 4][am] = ra1.x; As[nxt][ak + 5][am] = ra1.y;
            As[nxt][ak + 6][am] = ra1.z; As[nxt][ak + 7][am] = ra1.w;
            *(float4*)&Bs[nxt][br][bc]     = rb0;
            *(float4*)&Bs[nxt][br][bc + 4] = rb1;
        }
        __syncthreads();
        cur ^= 1;
    }
#pragma unroll
    for (int i = 0; i < 8; i++) {
        int row = brow + wr + lr * 8 + i;
        if (row < N_NODES) {
            float4 o = make_float4(acc[i][0], acc[i][1], acc[i][2], acc[i][3]);
            *(float4*)(g_H + (size_t)row * CAT + bcol + wc + lc * 4) = o;
        }
    }
}

// ---------------- 5. src/dst per head -> [node][head] ------------------------
__global__ void srcdst1(const float* __restrict__ a_heads) {
    int i = blockIdx.x;
    int head = threadIdx.x >> 5, lane = threadIdx.x & 31;
    const float* h = g_H + (size_t)i * CAT + head * HID;
    const float* a = a_heads + head * (2 * HID);
    float h0 = h[lane], h1 = h[lane + 32];
    float s = h0 * a[lane]      + h1 * a[lane + 32];
    float d = h0 * a[64 + lane] + h1 * a[96 + lane];
#pragma unroll
    for (int o = 16; o; o >>= 1) {
        s += __shfl_xor_sync(0xffffffffu, s, o);
        d += __shfl_xor_sync(0xffffffffu, d, o);
    }
    if (lane == 0) {
        g_srcT[i * HEADS + head] = s;
        g_dstT[i * HEADS + head] = d;
    }
}

// ---------------- 6. layer-1 sparse attention (block/row, warp/head) ---------
__global__ __launch_bounds__(256) void attn1() {
    int i = blockIdx.x;
    int tid = threadIdx.x;
    int head = tid >> 5, lane = tid & 31;
    __shared__ int   s_cols[MAXDEG];
    __shared__ float s_w[MAXDEG];
    __shared__ float s_p[HEADS][MAXDEG];
    int n = g_cnt[i];
    for (int k = tid; k < n; k += 256) {
        s_cols[k] = g_cols[i * MAXDEG + k];
        s_w[k]    = g_wv [i * MAXDEG + k];
    }
    __syncthreads();

    float si = g_srcT[i * HEADS + head];
    float m = -1e30f;
    for (int k = lane; k < n; k += 32) {
        float e = lrelu(si + __ldg(g_dstT + s_cols[k] * HEADS + head));
        s_p[head][k] = e;
        m = fmaxf(m, e);
    }
#pragma unroll
    for (int o = 16; o; o >>= 1) m = fmaxf(m, __shfl_xor_sync(0xffffffffu, m, o));
    float s = 0.f;
    for (int k = lane; k < n; k += 32) {
        float p = __expf(s_p[head][k] - m);
        s_p[head][k] = p;
        s += p;
    }
#pragma unroll
    for (int o = 16; o; o >>= 1) s += __shfl_xor_sync(0xffffffffu, s, o);
    float inv = 1.f / s;
    __syncwarp();

    const float2* Hb = (const float2*)g_H;
    float2 acc = make_float2(0.f, 0.f);
#pragma unroll 4
    for (int k = 0; k < n; k++) {
        int j = s_cols[k];
        float coef = s_p[head][k] * inv * s_w[k];
        float2 v = __ldg(Hb + (size_t)j * (CAT / 2) + head * 32 + lane);
        acc.x = fmaf(coef, v.x, acc.x);
        acc.y = fmaf(coef, v.y, acc.y);
    }
    float2 o = make_float2(elu1(acc.x), elu1(acc.y));
    ((float2*)g_X1)[(size_t)i * (CAT / 2) + head * 32 + lane] = o;
}

// ---------------- 7. H2 = X1 @ W_out, src2/dst2 ------------------------------
__global__ void h2_srcdst(const float* __restrict__ W_out,
                          const float* __restrict__ a_out) {
    int i = blockIdx.x, tid = threadIdx.x;
    __shared__ float sx[CAT];
    __shared__ float sp[16][17];
    __shared__ float sh[NCLASS];
    sx[tid]       = g_X1[(size_t)i * CAT + tid];
    sx[tid + 256] = g_X1[(size_t)i * CAT + tid + 256];
    __syncthreads();
    int c = tid & 15, chunk = tid >> 4;
    float p = 0.f;
    int k0 = chunk * 32;
#pragma unroll 8
    for (int k = k0; k < k0 + 32; k++) p = fmaf(sx[k], __ldg(W_out + k * NCLASS + c), p);
    sp[chunk][c] = p;
    __syncthreads();
    if (tid < NCLASS) {
        float v = 0.f;
#pragma unroll
        for (int q = 0; q < 16; q++) v += sp[q][tid];
        g_H2[i * NCLASS + tid] = v;
        sh[tid] = v;
    }
    __syncthreads();
    if (tid == 0) {
        float s = 0.f, d = 0.f;
#pragma unroll
        for (int cc = 0; cc < NCLASS; cc++) {
            s = fmaf(sh[cc], __ldg(a_out + cc), s);
            d = fmaf(sh[cc], __ldg(a_out + NCLASS + cc), d);
        }
        g_s2[i] = s;
        g_d2[i] = d;
    }
}

// ---------------- 8. layer-2 sparse attention (warp per row) -----------------
__global__ void attn2() {
    int w = threadIdx.x >> 5, lane = threadIdx.x & 31;
    int i = blockIdx.x * 4 + w;
    __shared__ int   s_c[4][MAXDEG];
    __shared__ float s_w[4][MAXDEG];
    __shared__ float s_p[4][MAXDEG];
    if (i >= N_NODES) return;
    int n = g_cnt[i];
    float si = g_s2[i];
    float m = -1e30f;
    for (int k = lane; k < n; k += 32) {
        int j = g_cols[i * MAXDEG + k];
        s_c[w][k] = j;
        s_w[w][k] = g_wv[i * MAXDEG + k];
        float e = lrelu(si + g_d2[j]);
        s_p[w][k] = e;
        m = fmaxf(m, e);
    }
#pragma unroll
    for (int o = 16; o; o >>= 1) m = fmaxf(m, __shfl_xor_sync(0xffffffffu, m, o));
    float s = 0.f;
    for (int k = lane; k < n; k += 32) {
        float p = __expf(s_p[w][k] - m);
        s_p[w][k] = p;
        s += p;
    }
#pragma unroll
    for (int o = 16; o; o >>= 1) s += __shfl_xor_sync(0xffffffffu, s, o);
    float inv = 1.f / s;
    __syncwarp();
    if (lane < NCLASS) {
        float acc = 0.f;
        for (int k = 0; k < n; k++) {
            float coef = s_p[w][k] * inv * s_w[w][k];
            acc = fmaf(coef, g_H2[s_c[w][k] * NCLASS + lane], acc);
        }
        g_Z[i * NCLASS + lane] = elu1(elu1(acc));
    }
}

// ---------------- 9. FC head + log_softmax (warp per row) --------------------
__global__ void head_k(const float* __restrict__ FC1,
                       const float* __restrict__ FC2,
                       float* __restrict__ out) {
    int w = threadIdx.x >> 5, lane = threadIdx.x & 31;
    int row = blockIdx.x * 8 + w;
    if (row >= N_NODES) return;
    float z = (lane < NCLASS) ? g_Z[row * NCLASS + lane] : 0.f;
    float y1 = 0.f;
#pragma unroll
    for (int k = 0; k < NCLASS; k++) {
        float zk = __shfl_sync(0xffffffffu, z, k);
        if (lane < NCLASS) y1 = fmaf(zk, __ldg(FC1 + lane * NCLASS + k), y1);
    }
    y1 = elu1(y1);
    float y2 = 0.f;
#pragma unroll
    for (int k = 0; k < NCLASS; k++) {
        float yk = __shfl_sync(0xffffffffu, y1, k);
        if (lane < NCLASS) y2 = fmaf(yk, __ldg(FC2 + lane * NCLASS + k), y2);
    }
    y2 = elu1(y2);
    float v = (lane < NCLASS) ? y2 : -1e30f;
#pragma unroll
    for (int o = 8; o; o >>= 1) v = fmaxf(v, __shfl_xor_sync(0xffffffffu, v, o));
    float e = (lane < NCLASS) ? expf(y2 - v) : 0.f;
    float sum = e;
#pragma unroll
    for (int o = 8; o; o >>= 1) sum += __shfl_xor_sync(0xffffffffu, sum, o);
    if (lane < NCLASS) out[row * NCLASS + lane] = y2 - v - logf(sum);
}

// ---------------- launcher ---------------------------------------------------
extern "C" void kernel_launch(void* const* d_in, const int* in_sizes, int n_in,
                              void* d_out, int out_size) {
    const float* adj     = (const float*)d_in[0];
    const float* feat    = (const float*)d_in[1];
    const float* W_heads = (const float*)d_in[2];
    const float* a_heads = (const float*)d_in[3];
    const float* W_out   = (const float*)d_in[4];
    const float* a_out   = (const float*)d_in[5];
    const float* FC1     = (const float*)d_in[6];
    const float* FC2     = (const float*)d_in[7];
    float* out = (float*)d_out;

    pack_w     <<<IN_DIM, CAT>>>(W_heads);
    build_edges<<<N_NODES, 128>>>(adj);
    wv_k       <<<(N_NODES * MAXDEG + 255) / 256, 256>>>();
    sgemm_H    <<<dim3(CAT / BN, (N_NODES + BM - 1) / BM), 128>>>(feat);
    srcdst1    <<<N_NODES, 256>>>(a_heads);
    attn1      <<<N_NODES, 256>>>();
    h2_srcdst  <<<N_NODES, 256>>>(W_out, a_out);
    attn2      <<<(N_NODES + 3) / 4, 128>>>();
    head_k     <<<(N_NODES + 7) / 8, 256>>>(FC1, FC2, out);
}